// round 15
// baseline (speedup 1.0000x reference)
#include <cuda_runtime.h>
#include <cuda_fp16.h>
#include <math.h>
#include <stdint.h>

// Problem constants
#define Bb 2
#define Nn 4096
#define Dd 512
#define Hh 8
#define Pp 9
#define GW 256
#define GH 16
#define Mrows 8192
#define Kdim 512
#define NT 8               // k-tiles of 64
#define NCAT 1792          // 512(q) + 1024(kv) + 256(off padded)

#define LAM    0.015625f   // 2^-6
#define LAMINV 64.0f
#define ONE_M_LAM 0.984375f

// ---------------- scratch (device globals) ----------------
__device__ float  g_q  [Mrows * Dd];
__device__ float  g_off[Mrows * Hh * Pp * 2];
__device__ float  g_kv [Mrows * 2 * Dd];                 // fp32 k/v maps
__device__ float  g_bcat[NCAT];
__device__ __half g_xh[Mrows * Kdim], g_x2[Mrows * Kdim];
__device__ __half g_wch[NCAT * Kdim], g_wc2[NCAT * Kdim];
__device__ __half g_woh[512 * Kdim],  g_wo2[512 * Kdim];
__device__ __half g_ah[Mrows * Kdim], g_a2[Mrows * Kdim];

// ---------------- helpers ----------------
__device__ __forceinline__ uint32_t smem_u32(const void* p) {
    uint32_t a;
    asm("{ .reg .u64 t; cvta.to.shared.u64 t, %1; cvt.u32.u64 %0, t; }" : "=r"(a) : "l"(p));
    return a;
}
__device__ __forceinline__ void cpa16(uint32_t dst, const void* g) {
    asm volatile("cp.async.cg.shared.global [%0], [%1], 16;" :: "r"(dst), "l"(g));
}
#define LDSM4(r, a) \
    asm volatile("ldmatrix.sync.aligned.m8n8.x4.shared.b16 {%0,%1,%2,%3}, [%4];" \
        : "=r"((r)[0]), "=r"((r)[1]), "=r"((r)[2]), "=r"((r)[3]) : "r"(a))

__device__ __forceinline__ void mma16816(float c[4],
        const uint32_t a[4], uint32_t b0, uint32_t b1) {
    asm volatile(
        "mma.sync.aligned.m16n8k16.row.col.f32.f16.f16.f32 "
        "{%0,%1,%2,%3},{%4,%5,%6,%7},{%8,%9},{%0,%1,%2,%3};"
        : "+f"(c[0]), "+f"(c[1]), "+f"(c[2]), "+f"(c[3])
        : "r"(a[0]), "r"(a[1]), "r"(a[2]), "r"(a[3]), "r"(b0), "r"(b1));
}

// SW128 swizzled smem byte offset within a 16KB plane (128 rows x 128B).
// chunk c (16B units, 0..7) XORed with row&7: conflict-free STS + LDSM.
__device__ __forceinline__ uint32_t swz(int row, int c) {
    return (uint32_t)(row * 128 + ((c ^ (row & 7)) << 4));
}

// lambda-split (activation): h = fl16(v); p2 = fl16(LAM*h + (v-h))
__device__ __forceinline__ void lam_split_a(float v, __half& h, __half& p2) {
    h = __float2half(v);
    float hf = __half2float(h);
    p2 = __float2half(fmaf(LAM, hf, v - hf));
}
// weight side: h = fl16(v); p2 = fl16(h + LAMINV*(v-h))
__device__ __forceinline__ void lam_split_b(float v, __half& h, __half& p2) {
    h = __float2half(v);
    float hf = __half2float(h);
    p2 = __float2half(fmaf(LAMINV, v - hf, hf));
}

// ---------------- converts ----------------
__global__ void convert_a(const float* __restrict__ src,
                          __half* __restrict__ Ph, __half* __restrict__ P2,
                          int total_pairs) {
    int i = blockIdx.x * blockDim.x + threadIdx.x;
    if (i >= total_pairs) return;
    float2 v = reinterpret_cast<const float2*>(src)[i];
    __half h0, h1, p0, p1;
    lam_split_a(v.x, h0, p0);
    lam_split_a(v.y, h1, p1);
    reinterpret_cast<__half2*>(Ph)[i] = __halves2half2(h0, h1);
    reinterpret_cast<__half2*>(P2)[i] = __halves2half2(p0, p1);
}

// one launch for all weights (unified row space 0..2303)
__global__ void convert_weights(const float* __restrict__ Wq,
                                const float* __restrict__ Wkv,
                                const float* __restrict__ Woff,
                                const float* __restrict__ Wo,
                                __half* __restrict__ wch, __half* __restrict__ wc2,
                                __half* __restrict__ woh, __half* __restrict__ wo2) {
    int i = blockIdx.x * blockDim.x + threadIdx.x;
    if (i >= 2304 * (Kdim / 2)) return;
    int m = i / (Kdim / 2), k = (i % (Kdim / 2)) * 2;
    const float* src = nullptr;
    __half *dh, *d2;
    int srow = 0, drow;
    if (m < 512)       { src = Wq;   srow = m;        dh = wch; d2 = wc2; drow = m; }
    else if (m < 1536) { src = Wkv;  srow = m - 512;  dh = wch; d2 = wc2; drow = m; }
    else if (m < 1792) { int r = m - 1536; src = (r < 144) ? Woff : nullptr; srow = r;
                         dh = wch; d2 = wc2; drow = m; }
    else               { src = Wo;   srow = m - 1792; dh = woh; d2 = wo2; drow = m - 1792; }
    float2 v = src ? *reinterpret_cast<const float2*>(src + (size_t)srow * Kdim + k)
                   : make_float2(0.f, 0.f);
    __half h0, h1, p0, p1;
    lam_split_b(v.x, h0, p0);
    lam_split_b(v.y, h1, p1);
    size_t o = ((size_t)drow * Kdim + k) >> 1;
    reinterpret_cast<__half2*>(dh)[o] = __halves2half2(h0, h1);
    reinterpret_cast<__half2*>(d2)[o] = __halves2half2(p0, p1);
}

__global__ void concat_bias(const float* bq, const float* bkv, const float* boff,
                            float* bcat) {
    int i = blockIdx.x * blockDim.x + threadIdx.x;
    if (i >= NCAT) return;
    float v = 0.f;
    if (i < 512) v = bq[i];
    else if (i < 1536) v = bkv[i - 512];
    else if (i < 1680) v = boff[i - 1536];
    bcat[i] = v;
}

// ---------------------------------------------------------------------------
// GEMM via lambda-compensated 2-term fp16 split:
//   C = (1-LAM)*(Ah @ Bh^T) + (A2 @ B2^T) + bias
// Block 128x128, BK=64, 3-stage cp.async (2 prefilled), 512 thr (16 warps).
// ONE barrier per k-tile; 8 k-tiles total (half the sync overhead of BK=32).
// MODE 0: fused x-GEMM routing to q/kv/off (tanh on off). MODE 1: plain Y.
// ---------------------------------------------------------------------------
#define PLANE_B 16384
#define STAGE_B 65536
#define SMEMSZ  (3 * STAGE_B)

template <int MODE>
__global__ __launch_bounds__(512, 1) void gemm_mma(
        const __half* __restrict__ Ah, const __half* __restrict__ A2,
        const __half* __restrict__ Bh, const __half* __restrict__ B2,
        const float* __restrict__ bias, float* __restrict__ Y,
        float* __restrict__ q_out, float* __restrict__ kv_out,
        float* __restrict__ off_out) {
    extern __shared__ char smem[];
    const uint32_t sb = smem_u32(smem);

    const int t    = threadIdx.x;
    const int m0   = blockIdx.y * 128;
    const int n0   = blockIdx.x * 128;
    const int wid  = t >> 5;
    const int lane = t & 31;
    const int gid  = lane >> 2;
    const int tg   = lane & 3;
    const int wm   = wid & 3;     // 4 warps in M
    const int wn   = wid >> 2;    // 4 warps in N

    float c1[2][4][4] = {};
    float c2[2][4][4] = {};

    // 4 planes x 128 rows x 8 chunks(16B); 512 threads -> 2 chunks/plane/thread
    auto issue = [&](int kt) {
        const uint32_t stg = sb + (kt % 3) * STAGE_B;
#pragma unroll
        for (int plane = 0; plane < 4; plane++) {
            const __half* g = (plane == 0) ? Ah : (plane == 1) ? A2
                            : (plane == 2) ? Bh : B2;
            const int base = (plane < 2) ? m0 : n0;
#pragma unroll
            for (int q = 0; q < 2; q++) {
                const int idx = q * 512 + t;          // 0..1023
                const int row = idx >> 3, cc = idx & 7;
                cpa16(stg + plane * PLANE_B + swz(row, cc),
                      g + (size_t)(base + row) * Kdim + kt * 64 + cc * 8);
            }
        }
        asm volatile("cp.async.commit_group;");
    };

    issue(0); issue(1);                 // 2 of 3 stages prefilled

    const int aRow = wm * 32 + ((lane >> 3) & 1) * 8 + (lane & 7);
    const int aCb  = (lane >> 4) & 1;
    const int bRow = wn * 32 + ((lane >> 4) & 1) * 8 + (lane & 7);
    const int bCb  = (lane >> 3) & 1;

    for (int kt = 0; kt < NT; kt++) {
        asm volatile("cp.async.wait_group 1;");   // group kt complete (own)
        __syncthreads();                          // all copies visible; kt-1 compute done
        if (kt + 2 < NT) issue(kt + 2);
        else asm volatile("cp.async.commit_group;");   // keep group count uniform

        const uint32_t stg = sb + (kt % 3) * STAGE_B;
        const uint32_t pAh = stg,               pA2 = stg + PLANE_B;
        const uint32_t pBh = stg + 2 * PLANE_B, pB2 = stg + 3 * PLANE_B;

#pragma unroll
        for (int ks = 0; ks < 4; ks++) {
            uint32_t bh[8], b2[8];
#pragma unroll
            for (int jj = 0; jj < 2; jj++) {
                uint32_t off = swz(bRow + jj * 16, ks * 2 + bCb);
                LDSM4(&bh[jj * 4], pBh + off);
                LDSM4(&b2[jj * 4], pB2 + off);
            }
#pragma unroll
            for (int i = 0; i < 2; i++) {
                uint32_t ah[4], a2r[4];
                uint32_t off = swz(aRow + i * 16, ks * 2 + aCb);
                LDSM4(ah,  pAh + off);
                LDSM4(a2r, pA2 + off);
#pragma unroll
                for (int j = 0; j < 4; j++) {
                    mma16816(c1[i][j], ah,  bh[j * 2], bh[j * 2 + 1]);
                    mma16816(c2[i][j], a2r, b2[j * 2], b2[j * 2 + 1]);
                }
            }
        }
    }

    // ---- epilogue: v = (1-LAM)*c1 + c2 + bias ----
#pragma unroll
    for (int i = 0; i < 2; i++) {
        const int m = m0 + wm * 32 + i * 16 + gid;
#pragma unroll
        for (int j = 0; j < 4; j++) {
            const int ng = n0 + wn * 32 + j * 8 + tg * 2;
            float b0 = bias[ng], b1 = bias[ng + 1];
            float v00 = fmaf(ONE_M_LAM, c1[i][j][0], c2[i][j][0]) + b0;
            float v01 = fmaf(ONE_M_LAM, c1[i][j][1], c2[i][j][1]) + b1;
            float v10 = fmaf(ONE_M_LAM, c1[i][j][2], c2[i][j][2]) + b0;
            float v11 = fmaf(ONE_M_LAM, c1[i][j][3], c2[i][j][3]) + b1;
            if (MODE == 1) {
                *reinterpret_cast<float2*>(Y + (size_t)m * 512 + ng)       = make_float2(v00, v01);
                *reinterpret_cast<float2*>(Y + (size_t)(m + 8) * 512 + ng) = make_float2(v10, v11);
            } else {
                if (ng < 512) {
                    *reinterpret_cast<float2*>(q_out + (size_t)m * 512 + ng)       = make_float2(v00, v01);
                    *reinterpret_cast<float2*>(q_out + (size_t)(m + 8) * 512 + ng) = make_float2(v10, v11);
                } else if (ng < 1536) {
                    int cc = ng - 512;
                    *reinterpret_cast<float2*>(kv_out + (size_t)m * 1024 + cc)       = make_float2(v00, v01);
                    *reinterpret_cast<float2*>(kv_out + (size_t)(m + 8) * 1024 + cc) = make_float2(v10, v11);
                } else {
                    int cc = ng - 1536;
                    if (cc < 144) {
                        *reinterpret_cast<float2*>(off_out + (size_t)m * 144 + cc) =
                            make_float2(tanhf(v00), tanhf(v01));
                        *reinterpret_cast<float2*>(off_out + (size_t)(m + 8) * 144 + cc) =
                            make_float2(tanhf(v10), tanhf(v11));
                    }
                }
            }
        }
    }
}

// ---------------- deformable sampling + attention (round-8 body) ----------
// One warp per (b,n,h). Lanes 0-15 own k dims (4 each), lanes 16-31 own v dims.
__global__ void attn_kernel(const float* __restrict__ q,
                            const float* __restrict__ off,
                            const float* __restrict__ kv,
                            __half* __restrict__ ah,
                            __half* __restrict__ a2) {
    int gw   = (blockIdx.x * blockDim.x + threadIdx.x) >> 5;
    int lane = threadIdx.x & 31;
    if (gw >= Bb * Nn * Hh) return;

    int hh = gw & 7;
    int n  = (gw >> 3) & 4095;
    int b  = gw >> 15;
    size_t row = (size_t)(b * Nn + n);

    const bool isK = lane < 16;
    const int d4 = (lane & 15) * 4;

    float4 q4 = make_float4(0.f, 0.f, 0.f, 0.f);
    if (isK) q4 = *reinterpret_cast<const float4*>(q + row * Dd + hh * 64 + d4);

    float bx = (float)(n & 255);
    float by = (float)(n >> 8);
    const float* offp = off + row * (Hh * Pp * 2) + hh * Pp * 2;
    const float* kvb  = kv + (size_t)b * Nn * 1024;
    const int laneoff = (isK ? 0 : 512) + hh * 64 + d4;

    float lg[Pp];
    float4 sv[Pp];

#pragma unroll
    for (int p = 0; p < Pp; p++) {
        float sx = bx + 4.0f * offp[2 * p];
        float sy = by + 4.0f * offp[2 * p + 1];
        float x0f = floorf(sx), y0f = floorf(sy);
        int   x0 = (int)x0f,  y0 = (int)y0f;
        float wx1 = sx - x0f, wy1 = sy - y0f;
        float wx0 = 1.0f - wx1, wy0 = 1.0f - wy1;

        float4 acc = make_float4(0.f, 0.f, 0.f, 0.f);
#pragma unroll
        for (int cc = 0; cc < 4; cc++) {
            int   xi = x0 + (cc & 1);
            int   yi = y0 + (cc >> 1);
            float wg = ((cc & 1) ? wx1 : wx0) * ((cc >> 1) ? wy1 : wy0);
            if (xi >= 0 && xi < GW && yi >= 0 && yi < GH) {
                float4 tv = *reinterpret_cast<const float4*>(
                    kvb + (size_t)(yi * GW + xi) * 1024 + laneoff);
                acc.x = fmaf(wg, tv.x, acc.x);
                acc.y = fmaf(wg, tv.y, acc.y);
                acc.z = fmaf(wg, tv.z, acc.z);
                acc.w = fmaf(wg, tv.w, acc.w);
            }
        }
        float d = isK ? (q4.x * acc.x + q4.y * acc.y + q4.z * acc.z + q4.w * acc.w) : 0.f;
#pragma unroll
        for (int s = 16; s > 0; s >>= 1)
            d += __shfl_xor_sync(0xffffffffu, d, s);
        lg[p] = d * 0.125f;
        sv[p] = acc;
    }

    float mx = lg[0];
#pragma unroll
    for (int p = 1; p < Pp; p++) mx = fmaxf(mx, lg[p]);
    float se = 0.f, wp[Pp];
#pragma unroll
    for (int p = 0; p < Pp; p++) { wp[p] = __expf(lg[p] - mx); se += wp[p]; }
    float inv = 1.0f / se;

    float4 o = make_float4(0.f, 0.f, 0.f, 0.f);
#pragma unroll
    for (int p = 0; p < Pp; p++) {
        o.x = fmaf(wp[p], sv[p].x, o.x);
        o.y = fmaf(wp[p], sv[p].y, o.y);
        o.z = fmaf(wp[p], sv[p].z, o.z);
        o.w = fmaf(wp[p], sv[p].w, o.w);
    }

    if (!isK) {
        o.x *= inv; o.y *= inv; o.z *= inv; o.w *= inv;
        size_t addr = row * Dd + hh * 64 + d4;
        __half h0, h1, h2, h3, p0, p1, p2, p3;
        lam_split_a(o.x, h0, p0);
        lam_split_a(o.y, h1, p1);
        lam_split_a(o.z, h2, p2);
        lam_split_a(o.w, h3, p3);
        reinterpret_cast<__half2*>(ah + addr)[0] = __halves2half2(h0, h1);
        reinterpret_cast<__half2*>(ah + addr)[1] = __halves2half2(h2, h3);
        reinterpret_cast<__half2*>(a2 + addr)[0] = __halves2half2(p0, p1);
        reinterpret_cast<__half2*>(a2 + addr)[1] = __halves2half2(p2, p3);
    }
}

// ---------------------------------------------------------------------------
extern "C" void kernel_launch(void* const* d_in, const int* in_sizes, int n_in,
                              void* d_out, int out_size) {
    const float* x    = (const float*)d_in[0];
    const float* Wq   = (const float*)d_in[1];
    const float* bq   = (const float*)d_in[2];
    const float* Woff = (const float*)d_in[3];
    const float* boff = (const float*)d_in[4];
    const float* Wkv  = (const float*)d_in[5];
    const float* bkv  = (const float*)d_in[6];
    const float* Wo   = (const float*)d_in[7];
    const float* bo   = (const float*)d_in[8];
    float* out = (float*)d_out;

    float *qb, *offb, *kvb, *bcat;
    __half *xh, *x2, *wch, *wc2, *woh, *wo2, *ah, *a2;
    cudaGetSymbolAddress((void**)&qb,   g_q);
    cudaGetSymbolAddress((void**)&offb, g_off);
    cudaGetSymbolAddress((void**)&kvb,  g_kv);
    cudaGetSymbolAddress((void**)&bcat, g_bcat);
    cudaGetSymbolAddress((void**)&xh,  g_xh);  cudaGetSymbolAddress((void**)&x2,  g_x2);
    cudaGetSymbolAddress((void**)&wch, g_wch); cudaGetSymbolAddress((void**)&wc2, g_wc2);
    cudaGetSymbolAddress((void**)&woh, g_woh); cudaGetSymbolAddress((void**)&wo2, g_wo2);
    cudaGetSymbolAddress((void**)&ah,  g_ah);  cudaGetSymbolAddress((void**)&a2,  g_a2);

    convert_a<<<(Mrows * Kdim / 2 + 255) / 256, 256>>>(x, xh, x2, Mrows * Kdim / 2);
    convert_weights<<<(2304 * (Kdim / 2) + 255) / 256, 256>>>(
        Wq, Wkv, Woff, Wo, wch, wc2, woh, wo2);
    concat_bias<<<(NCAT + 255) / 256, 256>>>(bq, bkv, boff, bcat);

    cudaFuncSetAttribute(gemm_mma<0>, cudaFuncAttributeMaxDynamicSharedMemorySize, SMEMSZ);
    cudaFuncSetAttribute(gemm_mma<1>, cudaFuncAttributeMaxDynamicSharedMemorySize, SMEMSZ);

    // fused: [q | kv | off] = x @ Wcat^T + bcat (tanh on off region)
    gemm_mma<0><<<dim3(NCAT / 128, Mrows / 128), 512, SMEMSZ>>>(
        xh, x2, wch, wc2, bcat, nullptr, qb, kvb, offb);

    // deformable sampling + attention (writes att hi / lambda planes)
    attn_kernel<<<(Bb * Nn * Hh) / 4, 128>>>(qb, offb, kvb, ah, a2);

    // out = att @ Wo^T + bo -> d_out
    gemm_mma<1><<<dim3(4, Mrows / 128), 512, SMEMSZ>>>(
        ah, a2, woh, wo2, bo, out, nullptr, nullptr, nullptr);
}

// round 16
// speedup vs baseline: 1.0467x; 1.0467x over previous
#include <cuda_runtime.h>
#include <cuda_fp16.h>
#include <math.h>
#include <stdint.h>

// Problem constants
#define Bb 2
#define Nn 4096
#define Dd 512
#define Hh 8
#define Pp 9
#define GW 256
#define GH 16
#define Mrows 8192
#define Kdim 512
#define NT 16              // k-tiles of 32
#define NCAT 1792          // 512(q) + 1024(kv) + 256(off padded)

#define LAM    0.015625f   // 2^-6
#define LAMINV 64.0f
#define ONE_M_LAM 0.984375f

// ---------------- scratch (device globals) ----------------
__device__ float  g_q  [Mrows * Dd];
__device__ float  g_off[Mrows * Hh * Pp * 2];
__device__ float  g_kv [Mrows * 2 * Dd];                 // fp32 k/v maps
__device__ float  g_bcat[NCAT];
__device__ __half g_xh[Mrows * Kdim], g_x2[Mrows * Kdim];
__device__ __half g_wch[NCAT * Kdim], g_wc2[NCAT * Kdim];
__device__ __half g_woh[512 * Kdim],  g_wo2[512 * Kdim];
__device__ __half g_ah[Mrows * Kdim], g_a2[Mrows * Kdim];

// ---------------- helpers ----------------
__device__ __forceinline__ uint32_t smem_u32(const void* p) {
    uint32_t a;
    asm("{ .reg .u64 t; cvta.to.shared.u64 t, %1; cvt.u32.u64 %0, t; }" : "=r"(a) : "l"(p));
    return a;
}
__device__ __forceinline__ void cpa16(uint32_t dst, const void* g) {
    asm volatile("cp.async.cg.shared.global [%0], [%1], 16;" :: "r"(dst), "l"(g));
}
#define LDSM4(r, a) \
    asm volatile("ldmatrix.sync.aligned.m8n8.x4.shared.b16 {%0,%1,%2,%3}, [%4];" \
        : "=r"((r)[0]), "=r"((r)[1]), "=r"((r)[2]), "=r"((r)[3]) : "r"(a))

__device__ __forceinline__ void mma16816(float c[4],
        const uint32_t a[4], uint32_t b0, uint32_t b1) {
    asm volatile(
        "mma.sync.aligned.m16n8k16.row.col.f32.f16.f16.f32 "
        "{%0,%1,%2,%3},{%4,%5,%6,%7},{%8,%9},{%0,%1,%2,%3};"
        : "+f"(c[0]), "+f"(c[1]), "+f"(c[2]), "+f"(c[3])
        : "r"(a[0]), "r"(a[1]), "r"(a[2]), "r"(a[3]), "r"(b0), "r"(b1));
}

// swizzled smem byte offset within an 8KB plane (128 rows x 64B)
__device__ __forceinline__ uint32_t swz(int row, int c) {
    return (uint32_t)(row * 64 + ((c ^ ((row >> 1) & 3)) << 4));
}

// lambda-split (activation): h = fl16(v); p2 = fl16(LAM*h + (v-h))
__device__ __forceinline__ void lam_split_a(float v, __half& h, __half& p2) {
    h = __float2half(v);
    float hf = __half2float(h);
    p2 = __float2half(fmaf(LAM, hf, v - hf));
}
// weight side: h = fl16(v); p2 = fl16(h + LAMINV*(v-h))
__device__ __forceinline__ void lam_split_b(float v, __half& h, __half& p2) {
    h = __float2half(v);
    float hf = __half2float(h);
    p2 = __float2half(fmaf(LAMINV, v - hf, hf));
}

// ---------------- fused prep: x split + all weight splits + bias concat ----
// index space (float2 pairs):
//   [0, 2097152)            -> x rows (activation-side split)
//   [2097152, 2687232)      -> unified weight rows 0..2303 (weight-side split)
// bias concat handled by first NCAT threads (extra branch, trivial).
#define XPAIRS (Mrows * Kdim / 2)              // 2097152
#define WPAIRS (2304 * (Kdim / 2))             // 589824
__global__ void prep_all(const float* __restrict__ x,
                         const float* __restrict__ Wq,
                         const float* __restrict__ Wkv,
                         const float* __restrict__ Woff,
                         const float* __restrict__ Wo,
                         const float* __restrict__ bq,
                         const float* __restrict__ bkv,
                         const float* __restrict__ boff,
                         __half* __restrict__ xh,  __half* __restrict__ x2,
                         __half* __restrict__ wch, __half* __restrict__ wc2,
                         __half* __restrict__ woh, __half* __restrict__ wo2,
                         float* __restrict__ bcat) {
    int i = blockIdx.x * blockDim.x + threadIdx.x;
    if (i < NCAT) {
        float v = 0.f;
        if (i < 512) v = bq[i];
        else if (i < 1536) v = bkv[i - 512];
        else if (i < 1680) v = boff[i - 1536];
        bcat[i] = v;
    }
    if (i < XPAIRS) {
        float2 v = reinterpret_cast<const float2*>(x)[i];
        __half h0, h1, p0, p1;
        lam_split_a(v.x, h0, p0);
        lam_split_a(v.y, h1, p1);
        reinterpret_cast<__half2*>(xh)[i] = __halves2half2(h0, h1);
        reinterpret_cast<__half2*>(x2)[i] = __halves2half2(p0, p1);
        return;
    }
    int wi = i - XPAIRS;
    if (wi >= WPAIRS) return;
    int m = wi / (Kdim / 2), k = (wi % (Kdim / 2)) * 2;
    const float* src = nullptr;
    __half *dh, *d2;
    int srow = 0, drow;
    if (m < 512)       { src = Wq;   srow = m;        dh = wch; d2 = wc2; drow = m; }
    else if (m < 1536) { src = Wkv;  srow = m - 512;  dh = wch; d2 = wc2; drow = m; }
    else if (m < 1792) { int r = m - 1536; src = (r < 144) ? Woff : nullptr; srow = r;
                         dh = wch; d2 = wc2; drow = m; }
    else               { src = Wo;   srow = m - 1792; dh = woh; d2 = wo2; drow = m - 1792; }
    float2 v = src ? *reinterpret_cast<const float2*>(src + (size_t)srow * Kdim + k)
                   : make_float2(0.f, 0.f);
    __half h0, h1, p0, p1;
    lam_split_b(v.x, h0, p0);
    lam_split_b(v.y, h1, p1);
    size_t o = ((size_t)drow * Kdim + k) >> 1;
    reinterpret_cast<__half2*>(dh)[o] = __halves2half2(h0, h1);
    reinterpret_cast<__half2*>(d2)[o] = __halves2half2(p0, p1);
}

// ---------------------------------------------------------------------------
// GEMM via lambda-compensated 2-term fp16 split (round-13 config, measured best):
//   C = (1-LAM)*(Ah @ Bh^T) + (A2 @ B2^T) + bias
// Block 128x128, BK=32, 3-stage cp.async (2 prefilled), 512 thr (16 warps).
// ONE barrier per k-tile: wait_group 1 -> sync -> issue(kt+2) -> compute(kt).
// MODE 0: fused x-GEMM routing to q/kv/off (tanh on off). MODE 1: plain Y.
// ---------------------------------------------------------------------------
#define STAGE_B 32768
#define SMEMSZ  (3 * STAGE_B)

template <int MODE>
__global__ __launch_bounds__(512, 1) void gemm_mma(
        const __half* __restrict__ Ah, const __half* __restrict__ A2,
        const __half* __restrict__ Bh, const __half* __restrict__ B2,
        const float* __restrict__ bias, float* __restrict__ Y,
        float* __restrict__ q_out, float* __restrict__ kv_out,
        float* __restrict__ off_out) {
    extern __shared__ char smem[];
    const uint32_t sb = smem_u32(smem);

    const int t    = threadIdx.x;
    const int m0   = blockIdx.y * 128;
    const int n0   = blockIdx.x * 128;
    const int wid  = t >> 5;
    const int lane = t & 31;
    const int gid  = lane >> 2;
    const int tg   = lane & 3;
    const int wm   = wid & 3;     // 4 warps in M
    const int wn   = wid >> 2;    // 4 warps in N

    float c1[2][4][4] = {};
    float c2[2][4][4] = {};

    const int lrow = t >> 2, lcc = t & 3;
    auto issue = [&](int kt) {
        const uint32_t stg = sb + (kt % 3) * STAGE_B;
#pragma unroll
        for (int plane = 0; plane < 4; plane++) {
            const __half* g = (plane == 0) ? Ah : (plane == 1) ? A2
                            : (plane == 2) ? Bh : B2;
            const int grow = ((plane < 2) ? m0 : n0) + lrow;
            cpa16(stg + plane * 8192 + swz(lrow, lcc),
                  g + (size_t)grow * Kdim + kt * 32 + lcc * 8);
        }
        asm volatile("cp.async.commit_group;");
    };

    issue(0); issue(1);                 // 2 of 3 stages prefilled

    const int aRow = wm * 32 + ((lane >> 3) & 1) * 8 + (lane & 7);
    const int aCb  = (lane >> 4) & 1;
    const int bRow = wn * 32 + ((lane >> 4) & 1) * 8 + (lane & 7);
    const int bCb  = (lane >> 3) & 1;

    for (int kt = 0; kt < NT; kt++) {
        asm volatile("cp.async.wait_group 1;");   // group kt complete (own)
        __syncthreads();                          // all copies visible; kt-1 compute done
        if (kt + 2 < NT) issue(kt + 2);
        else asm volatile("cp.async.commit_group;");   // keep group count uniform

        const uint32_t stg = sb + (kt % 3) * STAGE_B;
        const uint32_t pAh = stg, pA2 = stg + 8192, pBh = stg + 16384, pB2 = stg + 24576;

#pragma unroll
        for (int ks = 0; ks < 2; ks++) {
            uint32_t bh[8], b2[8];
#pragma unroll
            for (int jj = 0; jj < 2; jj++) {
                uint32_t off = swz(bRow + jj * 16, ks * 2 + bCb);
                LDSM4(&bh[jj * 4], pBh + off);
                LDSM4(&b2[jj * 4], pB2 + off);
            }
#pragma unroll
            for (int i = 0; i < 2; i++) {
                uint32_t ah[4], a2r[4];
                uint32_t off = swz(aRow + i * 16, ks * 2 + aCb);
                LDSM4(ah,  pAh + off);
                LDSM4(a2r, pA2 + off);
#pragma unroll
                for (int j = 0; j < 4; j++) {
                    mma16816(c1[i][j], ah,  bh[j * 2], bh[j * 2 + 1]);
                    mma16816(c2[i][j], a2r, b2[j * 2], b2[j * 2 + 1]);
                }
            }
        }
    }

    // ---- epilogue: v = (1-LAM)*c1 + c2 + bias ----
#pragma unroll
    for (int i = 0; i < 2; i++) {
        const int m = m0 + wm * 32 + i * 16 + gid;
#pragma unroll
        for (int j = 0; j < 4; j++) {
            const int ng = n0 + wn * 32 + j * 8 + tg * 2;
            float b0 = bias[ng], b1 = bias[ng + 1];
            float v00 = fmaf(ONE_M_LAM, c1[i][j][0], c2[i][j][0]) + b0;
            float v01 = fmaf(ONE_M_LAM, c1[i][j][1], c2[i][j][1]) + b1;
            float v10 = fmaf(ONE_M_LAM, c1[i][j][2], c2[i][j][2]) + b0;
            float v11 = fmaf(ONE_M_LAM, c1[i][j][3], c2[i][j][3]) + b1;
            if (MODE == 1) {
                *reinterpret_cast<float2*>(Y + (size_t)m * 512 + ng)       = make_float2(v00, v01);
                *reinterpret_cast<float2*>(Y + (size_t)(m + 8) * 512 + ng) = make_float2(v10, v11);
            } else {
                if (ng < 512) {
                    *reinterpret_cast<float2*>(q_out + (size_t)m * 512 + ng)       = make_float2(v00, v01);
                    *reinterpret_cast<float2*>(q_out + (size_t)(m + 8) * 512 + ng) = make_float2(v10, v11);
                } else if (ng < 1536) {
                    int cc = ng - 512;
                    *reinterpret_cast<float2*>(kv_out + (size_t)m * 1024 + cc)       = make_float2(v00, v01);
                    *reinterpret_cast<float2*>(kv_out + (size_t)(m + 8) * 1024 + cc) = make_float2(v10, v11);
                } else {
                    int cc = ng - 1536;
                    if (cc < 144) {
                        *reinterpret_cast<float2*>(off_out + (size_t)m * 144 + cc) =
                            make_float2(tanhf(v00), tanhf(v01));
                        *reinterpret_cast<float2*>(off_out + (size_t)(m + 8) * 144 + cc) =
                            make_float2(tanhf(v10), tanhf(v11));
                    }
                }
            }
        }
    }
}

// ---------------- deformable sampling + attention (round-8 body) ----------
// One warp per (b,n,h). Lanes 0-15 own k dims (4 each), lanes 16-31 own v dims.
__global__ void attn_kernel(const float* __restrict__ q,
                            const float* __restrict__ off,
                            const float* __restrict__ kv,
                            __half* __restrict__ ah,
                            __half* __restrict__ a2) {
    int gw   = (blockIdx.x * blockDim.x + threadIdx.x) >> 5;
    int lane = threadIdx.x & 31;
    if (gw >= Bb * Nn * Hh) return;

    int hh = gw & 7;
    int n  = (gw >> 3) & 4095;
    int b  = gw >> 15;
    size_t row = (size_t)(b * Nn + n);

    const bool isK = lane < 16;
    const int d4 = (lane & 15) * 4;

    float4 q4 = make_float4(0.f, 0.f, 0.f, 0.f);
    if (isK) q4 = *reinterpret_cast<const float4*>(q + row * Dd + hh * 64 + d4);

    float bx = (float)(n & 255);
    float by = (float)(n >> 8);
    const float* offp = off + row * (Hh * Pp * 2) + hh * Pp * 2;
    const float* kvb  = kv + (size_t)b * Nn * 1024;
    const int laneoff = (isK ? 0 : 512) + hh * 64 + d4;

    float lg[Pp];
    float4 sv[Pp];

#pragma unroll
    for (int p = 0; p < Pp; p++) {
        float sx = bx + 4.0f * offp[2 * p];
        float sy = by + 4.0f * offp[2 * p + 1];
        float x0f = floorf(sx), y0f = floorf(sy);
        int   x0 = (int)x0f,  y0 = (int)y0f;
        float wx1 = sx - x0f, wy1 = sy - y0f;
        float wx0 = 1.0f - wx1, wy0 = 1.0f - wy1;

        float4 acc = make_float4(0.f, 0.f, 0.f, 0.f);
#pragma unroll
        for (int cc = 0; cc < 4; cc++) {
            int   xi = x0 + (cc & 1);
            int   yi = y0 + (cc >> 1);
            float wg = ((cc & 1) ? wx1 : wx0) * ((cc >> 1) ? wy1 : wy0);
            if (xi >= 0 && xi < GW && yi >= 0 && yi < GH) {
                float4 tv = *reinterpret_cast<const float4*>(
                    kvb + (size_t)(yi * GW + xi) * 1024 + laneoff);
                acc.x = fmaf(wg, tv.x, acc.x);
                acc.y = fmaf(wg, tv.y, acc.y);
                acc.z = fmaf(wg, tv.z, acc.z);
                acc.w = fmaf(wg, tv.w, acc.w);
            }
        }
        float d = isK ? (q4.x * acc.x + q4.y * acc.y + q4.z * acc.z + q4.w * acc.w) : 0.f;
#pragma unroll
        for (int s = 16; s > 0; s >>= 1)
            d += __shfl_xor_sync(0xffffffffu, d, s);
        lg[p] = d * 0.125f;
        sv[p] = acc;
    }

    float mx = lg[0];
#pragma unroll
    for (int p = 1; p < Pp; p++) mx = fmaxf(mx, lg[p]);
    float se = 0.f, wp[Pp];
#pragma unroll
    for (int p = 0; p < Pp; p++) { wp[p] = __expf(lg[p] - mx); se += wp[p]; }
    float inv = 1.0f / se;

    float4 o = make_float4(0.f, 0.f, 0.f, 0.f);
#pragma unroll
    for (int p = 0; p < Pp; p++) {
        o.x = fmaf(wp[p], sv[p].x, o.x);
        o.y = fmaf(wp[p], sv[p].y, o.y);
        o.z = fmaf(wp[p], sv[p].z, o.z);
        o.w = fmaf(wp[p], sv[p].w, o.w);
    }

    if (!isK) {
        o.x *= inv; o.y *= inv; o.z *= inv; o.w *= inv;
        size_t addr = row * Dd + hh * 64 + d4;
        __half h0, h1, h2, h3, p0, p1, p2, p3;
        lam_split_a(o.x, h0, p0);
        lam_split_a(o.y, h1, p1);
        lam_split_a(o.z, h2, p2);
        lam_split_a(o.w, h3, p3);
        reinterpret_cast<__half2*>(ah + addr)[0] = __halves2half2(h0, h1);
        reinterpret_cast<__half2*>(ah + addr)[1] = __halves2half2(h2, h3);
        reinterpret_cast<__half2*>(a2 + addr)[0] = __halves2half2(p0, p1);
        reinterpret_cast<__half2*>(a2 + addr)[1] = __halves2half2(p2, p3);
    }
}

// ---------------------------------------------------------------------------
extern "C" void kernel_launch(void* const* d_in, const int* in_sizes, int n_in,
                              void* d_out, int out_size) {
    const float* x    = (const float*)d_in[0];
    const float* Wq   = (const float*)d_in[1];
    const float* bq   = (const float*)d_in[2];
    const float* Woff = (const float*)d_in[3];
    const float* boff = (const float*)d_in[4];
    const float* Wkv  = (const float*)d_in[5];
    const float* bkv  = (const float*)d_in[6];
    const float* Wo   = (const float*)d_in[7];
    const float* bo   = (const float*)d_in[8];
    float* out = (float*)d_out;

    float *qb, *offb, *kvb, *bcat;
    __half *xh, *x2, *wch, *wc2, *woh, *wo2, *ah, *a2;
    cudaGetSymbolAddress((void**)&qb,   g_q);
    cudaGetSymbolAddress((void**)&offb, g_off);
    cudaGetSymbolAddress((void**)&kvb,  g_kv);
    cudaGetSymbolAddress((void**)&bcat, g_bcat);
    cudaGetSymbolAddress((void**)&xh,  g_xh);  cudaGetSymbolAddress((void**)&x2,  g_x2);
    cudaGetSymbolAddress((void**)&wch, g_wch); cudaGetSymbolAddress((void**)&wc2, g_wc2);
    cudaGetSymbolAddress((void**)&woh, g_woh); cudaGetSymbolAddress((void**)&wo2, g_wo2);
    cudaGetSymbolAddress((void**)&ah,  g_ah);  cudaGetSymbolAddress((void**)&a2,  g_a2);

    // one fused prep launch: x split + weight splits + bias concat
    prep_all<<<(XPAIRS + WPAIRS + 255) / 256, 256>>>(
        x, Wq, Wkv, Woff, Wo, bq, bkv, boff,
        xh, x2, wch, wc2, woh, wo2, bcat);

    cudaFuncSetAttribute(gemm_mma<0>, cudaFuncAttributeMaxDynamicSharedMemorySize, SMEMSZ);
    cudaFuncSetAttribute(gemm_mma<1>, cudaFuncAttributeMaxDynamicSharedMemorySize, SMEMSZ);

    // fused: [q | kv | off] = x @ Wcat^T + bcat (tanh on off region)
    gemm_mma<0><<<dim3(NCAT / 128, Mrows / 128), 512, SMEMSZ>>>(
        xh, x2, wch, wc2, bcat, nullptr, qb, kvb, offb);

    // deformable sampling + attention (512-thread blocks)
    attn_kernel<<<(Bb * Nn * Hh) / 16, 512>>>(qb, offb, kvb, ah, a2);

    // out = att @ Wo^T + bo -> d_out
    gemm_mma<1><<<dim3(4, Mrows / 128), 512, SMEMSZ>>>(
        ah, a2, woh, wo2, bo, out, nullptr, nullptr, nullptr);
}